// round 5
// baseline (speedup 1.0000x reference)
#include <cuda_runtime.h>

#define N 8192
#define D 128
#define BM 64
#define BN 32
#define SPLIT 4
#define NTHREADS 256
#define NTILES ((N / SPLIT) / BN)
#define ALPHA 0.2f
#define THRESH 0.5f

// ---------------- scratch (device globals: no allocation allowed) ----------------
__device__ __align__(16) float g_s1[N];
__device__ __align__(16) float g_s2[N];
__device__ float g_s2max;
__device__ __align__(16) float g_pacc[SPLIT * N * D];   // 16 MB partial accumulators
__device__ __align__(16) float g_pZ[SPLIT * N];

// ---------------- packed f32x2 helpers (sm_100+) ----------------
__device__ __forceinline__ unsigned long long pack2(float x, float y) {
    unsigned long long r;
    asm("mov.b64 %0, {%1, %2};" : "=l"(r) : "f"(x), "f"(y));
    return r;
}
__device__ __forceinline__ void unpack2(float& x, float& y, unsigned long long v) {
    asm("mov.b64 {%0, %1}, %2;" : "=f"(x), "=f"(y) : "l"(v));
}
__device__ __forceinline__ void ffma2(unsigned long long& d, unsigned long long a,
                                      unsigned long long b) {
    asm("fma.rn.f32x2 %0, %1, %2, %0;" : "+l"(d) : "l"(a), "l"(b));
}

// ---------------- kernel 1: s1 = nodes@a1, s2 = nodes@a2 (one warp per row) ------
__global__ void scores_kernel(const float* __restrict__ nodes, const float* __restrict__ a) {
    int row  = blockIdx.x * 8 + (threadIdx.x >> 5);
    int lane = threadIdx.x & 31;
    float4 x  = ((const float4*)nodes)[row * 32 + lane];
    float4 A1 = ((const float4*)a)[lane];        // a[0:128]
    float4 A2 = ((const float4*)a)[32 + lane];   // a[128:256]
    float d1 = x.x * A1.x + x.y * A1.y + x.z * A1.z + x.w * A1.w;
    float d2 = x.x * A2.x + x.y * A2.y + x.z * A2.z + x.w * A2.w;
#pragma unroll
    for (int o = 16; o > 0; o >>= 1) {
        d1 += __shfl_xor_sync(0xffffffff, d1, o);
        d2 += __shfl_xor_sync(0xffffffff, d2, o);
    }
    if (lane == 0) { g_s1[row] = d1; g_s2[row] = d2; }
}

// ---------------- kernel 2: global max of s2 -------------------------------------
__global__ void s2max_kernel() {
    __shared__ float sm[256];
    int t = threadIdx.x;
    float m = -1e30f;
    for (int j = t; j < N; j += 256) m = fmaxf(m, g_s2[j]);
    sm[t] = m;
    __syncthreads();
    for (int o = 128; o > 0; o >>= 1) {
        if (t < o) sm[t] = fmaxf(sm[t], sm[t + o]);
        __syncthreads();
    }
    if (t == 0) g_s2max = sm[0];
}

// ---------------- kernel 3: fused mask + exp + PV GEMM (per j-split partials) ----
__global__ __launch_bounds__(NTHREADS, 2) void attn_kernel(const float* __restrict__ nodes,
                                                           const float* __restrict__ dist) {
    __shared__ __align__(16) float sWt[BN][BM + 4];  // W transposed: [jj][row], 32x68
    __shared__ __align__(16) float sX[BN][D];        // nodes tile:   32x128
    __shared__ float sS1[BM];
    __shared__ float sM[BM];
    __shared__ float sZ[BM];

    const int t  = threadIdx.x;
    const int i0 = blockIdx.x * BM;
    const int jbase = blockIdx.y * (N / SPLIT);

    if (t < BM) {
        float s1 = g_s1[i0 + t];
        sS1[t] = s1;
        float u = s1 + g_s2max;
        sM[t] = fmaxf(u, ALPHA * u);  // per-row softmax upper bound (lrelu monotone)
        sZ[t] = 0.f;
    }

    // W/dist loader mapping: 4 threads per i-row, 8 consecutive jj each
    const int ldr = t >> 2;
    const int ldc = (t & 3) * 8;

    // GEMM mapping: thread -> rows [ty*4, ty*4+4), cols [tx*8, tx*8+8)
    const int ty = t >> 4;
    const int tx = t & 15;

    unsigned long long acc[4][4];
#pragma unroll
    for (int r = 0; r < 4; ++r)
#pragma unroll
        for (int q = 0; q < 4; ++q) acc[r][q] = 0ull;

    // prefetch tile 0 (dist + nodes) into registers
    float4 dA0, dA1, xP[4];
    {
        const float* drow = dist + (size_t)(i0 + ldr) * N + jbase + ldc;
        dA0 = ((const float4*)drow)[0];
        dA1 = ((const float4*)drow)[1];
        const float4* nsrc = (const float4*)(nodes + (size_t)jbase * D);
#pragma unroll
        for (int k = 0; k < 4; ++k) xP[k] = nsrc[t + k * NTHREADS];
    }

    for (int tile = 0; tile < NTILES; ++tile) {
        const int j0 = jbase + tile * BN;
        __syncthreads();  // previous GEMM finished reading smem

        // ---- build W tile (masked exp weights), transposed, + row-sum Z ----
        {
            float4 q0 = ((const float4*)(g_s2 + j0 + ldc))[0];
            float4 q1 = ((const float4*)(g_s2 + j0 + ldc))[1];
            float s1 = sS1[ldr], M = sM[ldr];
            float dd[8] = {dA0.x, dA0.y, dA0.z, dA0.w, dA1.x, dA1.y, dA1.z, dA1.w};
            float ss[8] = {q0.x, q0.y, q0.z, q0.w, q1.x, q1.y, q1.z, q1.w};
            float zpart = 0.f;
#pragma unroll
            for (int u = 0; u < 8; ++u) {
                float e = s1 + ss[u];
                e = fmaxf(e, ALPHA * e);                       // leaky_relu
                float wv = (dd[u] < THRESH) ? __expf(e - M) : 0.f;
                sWt[ldc + u][ldr] = wv;
                zpart += wv;
            }
            zpart += __shfl_xor_sync(0xffffffff, zpart, 1);
            zpart += __shfl_xor_sync(0xffffffff, zpart, 2);
            if ((t & 3) == 0) sZ[ldr] += zpart;
        }
        // ---- stage nodes tile ----
        {
            float4* xdst = (float4*)sX;
#pragma unroll
            for (int k = 0; k < 4; ++k) xdst[t + k * NTHREADS] = xP[k];
        }
        __syncthreads();  // tiles ready

        // ---- prefetch next tile while GEMM runs ----
        if (tile + 1 < NTILES) {
            const int jn = j0 + BN;
            const float* drow = dist + (size_t)(i0 + ldr) * N + jn + ldc;
            dA0 = ((const float4*)drow)[0];
            dA1 = ((const float4*)drow)[1];
            const float4* nsrc = (const float4*)(nodes + (size_t)jn * D);
#pragma unroll
            for (int k = 0; k < 4; ++k) xP[k] = nsrc[t + k * NTHREADS];
        }

        // ---- GEMM: acc[r][:] += W[row][jj] * X[jj][:], packed f32x2 ----
#pragma unroll
        for (int jj = 0; jj < BN; ++jj) {
            const ulonglong2* xr = (const ulonglong2*)&sX[jj][tx * 8];
            ulonglong2 xa = xr[0];
            ulonglong2 xb = xr[1];
            float4 wv = *(const float4*)&sWt[jj][ty * 4];
            unsigned long long w0 = pack2(wv.x, wv.x);
            unsigned long long w1 = pack2(wv.y, wv.y);
            unsigned long long w2 = pack2(wv.z, wv.z);
            unsigned long long w3 = pack2(wv.w, wv.w);
            ffma2(acc[0][0], w0, xa.x); ffma2(acc[0][1], w0, xa.y);
            ffma2(acc[0][2], w0, xb.x); ffma2(acc[0][3], w0, xb.y);
            ffma2(acc[1][0], w1, xa.x); ffma2(acc[1][1], w1, xa.y);
            ffma2(acc[1][2], w1, xb.x); ffma2(acc[1][3], w1, xb.y);
            ffma2(acc[2][0], w2, xa.x); ffma2(acc[2][1], w2, xa.y);
            ffma2(acc[2][2], w2, xb.x); ffma2(acc[2][3], w2, xb.y);
            ffma2(acc[3][0], w3, xa.x); ffma2(acc[3][1], w3, xa.y);
            ffma2(acc[3][2], w3, xb.x); ffma2(acc[3][3], w3, xb.y);
        }
    }

    // ---- write partial acc + partial Z for this j-split ----
#pragma unroll
    for (int r = 0; r < 4; ++r) {
        int row = i0 + ty * 4 + r;
        float o[8];
        unpack2(o[0], o[1], acc[r][0]);
        unpack2(o[2], o[3], acc[r][1]);
        unpack2(o[4], o[5], acc[r][2]);
        unpack2(o[6], o[7], acc[r][3]);
        float* dst = g_pacc + ((size_t)blockIdx.y * N + row) * D + tx * 8;
        ((float4*)dst)[0] = make_float4(o[0], o[1], o[2], o[3]);
        ((float4*)dst)[1] = make_float4(o[4], o[5], o[6], o[7]);
        if (tx == 0) g_pZ[blockIdx.y * N + row] = sZ[ty * 4 + r];
    }
}

// ---------------- kernel 4: combine splits, normalize ----------------------------
__global__ void combine_kernel(float* __restrict__ out) {
    int f   = blockIdx.x * 256 + threadIdx.x;  // float4 index into N*D
    int row = f >> 5;                          // 32 float4 per row
    float4 s = ((const float4*)g_pacc)[f];
    float Z  = g_pZ[row];
#pragma unroll
    for (int p = 1; p < SPLIT; ++p) {
        float4 v = ((const float4*)g_pacc)[p * (N * D / 4) + f];
        s.x += v.x; s.y += v.y; s.z += v.z; s.w += v.w;
        Z += g_pZ[p * N + row];
    }
    float inv = 1.0f / Z;
    s.x *= inv; s.y *= inv; s.z *= inv; s.w *= inv;
    ((float4*)out)[f] = s;
}

// ---------------- launch ---------------------------------------------------------
extern "C" void kernel_launch(void* const* d_in, const int* in_sizes, int n_in,
                              void* d_out, int out_size) {
    const float* nodes = (const float*)d_in[0];  // [8192,128]
    const float* dist  = (const float*)d_in[1];  // [8192,8192]
    const float* a     = (const float*)d_in[2];  // [256,1]
    float* out = (float*)d_out;                  // [8192,128]

    scores_kernel<<<N / 8, 256>>>(nodes, a);
    s2max_kernel<<<1, 256>>>();
    dim3 grid(N / BM, SPLIT);
    attn_kernel<<<grid, NTHREADS>>>(nodes, dist);
    combine_kernel<<<N * D / 4 / 256, 256>>>(out);
}

// round 10
// speedup vs baseline: 3.5402x; 3.5402x over previous
#include <cuda_runtime.h>
#include <cuda_fp16.h>
#include <cstdint>

#define N 8192
#define D 128
#define BM 128
#define BK 64
#define SPLIT 2
#define JSPAN (N / SPLIT)       // 4096
#define NTILES (JSPAN / BK)     // 64 tiles per CTA
#define NJT (N / BK)            // 128 global j-tiles
#define NTHREADS 512
#define ALPHA 0.2f
#define THRESH 0.5f
#define LOG2E 1.4426950408889634f

// ---------------- device scratch (no allocation allowed) ----------------
__device__ __align__(16) float g_s1[N];
__device__ __align__(16) float g_s2[N];
__device__ float g_s2max;
// pre-swizzled X^T fp16 tiles: per j-tile, [k=64][n=128] fp16, 256B rows,
// 16B chunk swizzle: chunk' = chunk ^ (k&7). 16KB per tile.
__device__ __align__(16) unsigned char g_Xhi[(size_t)NJT * 16384];
__device__ __align__(16) unsigned char g_Xlo[(size_t)NJT * 16384];
__device__ __align__(16) float g_pacc[SPLIT * N * D];   // 8 MB fp32 partials
__device__ __align__(16) float g_pZ[SPLIT * N];

// ---------------- smem layout ----------------
// buffer b (0/1) at b*65536: Whi +0 (16K), Wlo +16384, Xhi +32768, Xlo +49152
// W tile layout: [i=128][k=64] fp16, 128B rows, chunk' = chunk ^ (i&7)
#define SM_S2   131072          // 4096 floats (s2 slice)
#define SM_Z    147456          // 128 floats
#define SMEM_TOTAL 147968

// ---------------- PTX helpers ----------------
__device__ __forceinline__ uint32_t smem_u32(const void* p) {
    uint32_t a;
    asm("{ .reg .u64 t; cvta.to.shared.u64 t, %1; cvt.u32.u64 %0, t; }" : "=r"(a) : "l"(p));
    return a;
}
#define CP16(dst, src) \
    asm volatile("cp.async.cg.shared.global [%0], [%1], 16;" :: "r"(dst), "l"(src) : "memory")
#define CP_COMMIT() asm volatile("cp.async.commit_group;" ::: "memory")
#define CP_WAIT1()  asm volatile("cp.async.wait_group 1;" ::: "memory")

#define LDSM4(r, a)                                                           \
    asm volatile("ldmatrix.sync.aligned.m8n8.x4.shared.b16 {%0,%1,%2,%3},[%4];" \
                 : "=r"((r)[0]), "=r"((r)[1]), "=r"((r)[2]), "=r"((r)[3]) : "r"(a))
#define LDSM4T(r, a)                                                          \
    asm volatile("ldmatrix.sync.aligned.m8n8.x4.trans.shared.b16 {%0,%1,%2,%3},[%4];" \
                 : "=r"((r)[0]), "=r"((r)[1]), "=r"((r)[2]), "=r"((r)[3]) : "r"(a))
#define MMA16816(d, a, b0, b1)                                                 \
    asm volatile("mma.sync.aligned.m16n8k16.row.col.f32.f16.f16.f32 "          \
                 "{%0,%1,%2,%3},{%4,%5,%6,%7},{%8,%9},{%0,%1,%2,%3};"          \
                 : "+f"((d)[0]), "+f"((d)[1]), "+f"((d)[2]), "+f"((d)[3])      \
                 : "r"((a)[0]), "r"((a)[1]), "r"((a)[2]), "r"((a)[3]),         \
                   "r"(b0), "r"(b1))

// ---------------- kernel 1: s1/s2 (one warp per row) ----------------
__global__ void scores_kernel(const float* __restrict__ nodes, const float* __restrict__ a) {
    int row = blockIdx.x * 8 + (threadIdx.x >> 5);
    int lane = threadIdx.x & 31;
    float4 x  = ((const float4*)nodes)[row * 32 + lane];
    float4 A1 = ((const float4*)a)[lane];
    float4 A2 = ((const float4*)a)[32 + lane];
    float d1 = x.x * A1.x + x.y * A1.y + x.z * A1.z + x.w * A1.w;
    float d2 = x.x * A2.x + x.y * A2.y + x.z * A2.z + x.w * A2.w;
#pragma unroll
    for (int o = 16; o > 0; o >>= 1) {
        d1 += __shfl_xor_sync(0xffffffff, d1, o);
        d2 += __shfl_xor_sync(0xffffffff, d2, o);
    }
    if (lane == 0) { g_s1[row] = d1; g_s2[row] = d2; }
}

// ---------------- kernel 2: max(s2) ----------------
__global__ void s2max_kernel() {
    __shared__ float sm[256];
    int t = threadIdx.x;
    float m = -1e30f;
    for (int j = t; j < N; j += 256) m = fmaxf(m, g_s2[j]);
    sm[t] = m;
    __syncthreads();
    for (int o = 128; o > 0; o >>= 1) {
        if (t < o) sm[t] = fmaxf(sm[t], sm[t + o]);
        __syncthreads();
    }
    if (t == 0) g_s2max = sm[0];
}

// ---------------- kernel 3: pre-swizzled X^T fp16 hi/lo tiles ----------------
__global__ void bprep_kernel(const float* __restrict__ nodes) {
    int g  = blockIdx.x * 256 + threadIdx.x;   // NJT * 64k * 64 npairs = 524288
    int np = g & 63;
    int k  = (g >> 6) & 63;
    int jt = g >> 12;
    int n0 = np * 2;
    const float* src = nodes + (size_t)(jt * 64 + k) * D + n0;
    float x0 = src[0], x1 = src[1];
    __half2 hp = __floats2half2_rn(x0, x1);    // x0 -> low half
    float2 hf = __half22float2(hp);
    __half2 lp = __floats2half2_rn(x0 - hf.x, x1 - hf.y);
    uint32_t off = k * 256 + (((n0 >> 3) ^ (k & 7)) * 16) + (n0 & 7) * 2;
    *(uint32_t*)(g_Xhi + (size_t)jt * 16384 + off) = *(uint32_t*)&hp;
    *(uint32_t*)(g_Xlo + (size_t)jt * 16384 + off) = *(uint32_t*)&lp;
}

// ---------------- kernel 4: fused W-build + HMMA PV GEMM ----------------
__global__ __launch_bounds__(NTHREADS, 1) void attn_kernel(const float* __restrict__ dist) {
    extern __shared__ __align__(1024) unsigned char smem[];
    const uint32_t sb = smem_u32(smem);
    const int t = threadIdx.x;
    const int l = t & 31;
    const int w = t >> 5;
    const int wr = w >> 2, wc = w & 3;        // warp tile: rows wr*32, cols wc*32
    const int i0 = blockIdx.x * BM;
    const int h  = blockIdx.y;
    const int jb = h * JSPAN;

    float* s2sh = (float*)(smem + SM_S2);
    float* sZ   = (float*)(smem + SM_Z);

    for (int i = t; i < JSPAN / 4; i += NTHREADS)
        ((float4*)s2sh)[i] = ((const float4*)(g_s2 + jb))[i];
    if (t < BM) sZ[t] = 0.f;
    __syncthreads();

    // W-build mapping: 4 threads per row, 16 consecutive k each
    const int r  = t >> 2;
    const int cq = (t & 3) * 16;
    const float s1v = g_s1[i0 + r];
    const float uu  = s1v + g_s2max;
    const float M   = fmaxf(uu, ALPHA * uu);  // softmax upper bound (lrelu monotone)
    const float Ml  = M * LOG2E;

    // ldmatrix addressing constants
    const int arow = wr * 32 + (l & 15);      // A row (mi adds 16)
    const int a7   = arow & 7;
    const int kb   = (l & 7) + ((l >> 3) & 1) * 8;   // B k-offset within kstep
    const int nch0 = wc * 4 + (l >> 4);
    const int scB0 = nch0 ^ (l & 7);
    const int scB1 = (nch0 + 2) ^ (l & 7);

    float acc[2][4][4];
#pragma unroll
    for (int mi = 0; mi < 2; ++mi)
#pragma unroll
        for (int ni = 0; ni < 4; ++ni)
#pragma unroll
            for (int e = 0; e < 4; ++e) acc[mi][ni][e] = 0.f;

    // preload: X tile 0 via cp.async, dist tile 0 into regs
    {
        const int jt0 = h * NTILES;
        const unsigned char* sH = g_Xhi + (size_t)jt0 * 16384;
        const unsigned char* sL = g_Xlo + (size_t)jt0 * 16384;
        uint32_t dH = sb + 32768, dL = sb + 49152;
        CP16(dH + t * 16, sH + t * 16);
        CP16(dH + 8192 + t * 16, sH + 8192 + t * 16);
        CP16(dL + t * 16, sL + t * 16);
        CP16(dL + 8192 + t * 16, sL + 8192 + t * 16);
        CP_COMMIT();
    }
    float4 dp[4];
    {
        const float4* dr = (const float4*)(dist + (size_t)(i0 + r) * N + jb + cq);
        dp[0] = dr[0]; dp[1] = dr[1]; dp[2] = dr[2]; dp[3] = dr[3];
    }

    for (int tl = 0; tl < NTILES; ++tl) {
        const int b = tl & 1;
        unsigned char* bufp = smem + b * 65536;

        // ---- phase A: build W hi/lo (masked exp weights) + Z ----
        {
            const float4* s2p = (const float4*)(s2sh + tl * BK + cq);
            uint32_t hw[8], lw[8];
            float zp = 0.f;
#pragma unroll
            for (int q = 0; q < 4; ++q) {
                float4 dd = dp[q];
                float4 ss = s2p[q];
                float dv[4] = {dd.x, dd.y, dd.z, dd.w};
                float sv[4] = {ss.x, ss.y, ss.z, ss.w};
                float wv[4];
#pragma unroll
                for (int e = 0; e < 4; ++e) {
                    float x = s1v + sv[e];
                    float lr = fmaxf(x, ALPHA * x);
                    float ev;
                    asm("ex2.approx.f32 %0, %1;" : "=f"(ev) : "f"(fmaf(lr, LOG2E, -Ml)));
                    ev = (dv[e] < THRESH) ? ev : 0.f;
                    wv[e] = ev;
                    zp += ev;
                }
                __half2 h0 = __floats2half2_rn(wv[0], wv[1]);
                __half2 h1 = __floats2half2_rn(wv[2], wv[3]);
                float2 f0 = __half22float2(h0);
                float2 f1 = __half22float2(h1);
                __half2 l0 = __floats2half2_rn(wv[0] - f0.x, wv[1] - f0.y);
                __half2 l1 = __floats2half2_rn(wv[2] - f1.x, wv[3] - f1.y);
                hw[2 * q]     = *(uint32_t*)&h0;
                hw[2 * q + 1] = *(uint32_t*)&h1;
                lw[2 * q]     = *(uint32_t*)&l0;
                lw[2 * q + 1] = *(uint32_t*)&l1;
            }
            int c0 = (cq >> 3) ^ (r & 7);
            int c1 = ((cq >> 3) + 1) ^ (r & 7);
            *(uint4*)(bufp + r * 128 + c0 * 16)         = make_uint4(hw[0], hw[1], hw[2], hw[3]);
            *(uint4*)(bufp + r * 128 + c1 * 16)         = make_uint4(hw[4], hw[5], hw[6], hw[7]);
            *(uint4*)(bufp + 16384 + r * 128 + c0 * 16) = make_uint4(lw[0], lw[1], lw[2], lw[3]);
            *(uint4*)(bufp + 16384 + r * 128 + c1 * 16) = make_uint4(lw[4], lw[5], lw[6], lw[7]);
            zp += __shfl_xor_sync(0xffffffff, zp, 1);
            zp += __shfl_xor_sync(0xffffffff, zp, 2);
            if ((t & 3) == 0) sZ[r] += zp;
        }

        // ---- issue cp.async for X(tl+1) into the other buffer ----
        if (tl + 1 < NTILES) {
            const int jt = h * NTILES + tl + 1;
            const unsigned char* sH = g_Xhi + (size_t)jt * 16384;
            const unsigned char* sL = g_Xlo + (size_t)jt * 16384;
            uint32_t dH = sb + (b ^ 1) * 65536 + 32768;
            uint32_t dL = dH + 16384;
            CP16(dH + t * 16, sH + t * 16);
            CP16(dH + 8192 + t * 16, sH + 8192 + t * 16);
            CP16(dL + t * 16, sL + t * 16);
            CP16(dL + 8192 + t * 16, sL + 8192 + t * 16);
        }
        CP_COMMIT();
        CP_WAIT1();          // X(tl) resident; X(tl+1) may remain in flight
        __syncthreads();

        // ---- phase B: prefetch next dist tile, then HMMA over this buffer ----
        if (tl + 1 < NTILES) {
            const float4* dr =
                (const float4*)(dist + (size_t)(i0 + r) * N + jb + (tl + 1) * BK + cq);
            dp[0] = dr[0]; dp[1] = dr[1]; dp[2] = dr[2]; dp[3] = dr[3];
        }

        const uint32_t WB  = sb + b * 65536;
        const uint32_t WLb = WB + 16384;
        const uint32_t XB  = WB + 32768;
        const uint32_t XLb = WB + 49152;
#pragma unroll
        for (int ks = 0; ks < 4; ++ks) {
            uint32_t aH[2][4], aL[2][4], bF[2][4];
            const int kc = ks * 2 + (l >> 4);
            const uint32_t aoff = arow * 128 + ((kc ^ a7) * 16);
            const uint32_t bo0 = (ks * 16 + kb) * 256 + scB0 * 16;
            const uint32_t bo1 = (ks * 16 + kb) * 256 + scB1 * 16;
            LDSM4(aH[0], WB + aoff);
            LDSM4(aH[1], WB + aoff + 2048);       // +16 rows * 128B
            LDSM4T(bF[0], XB + bo0);
            LDSM4T(bF[1], XB + bo1);
#pragma unroll
            for (int mi = 0; mi < 2; ++mi) {      // Whi * Xhi
                MMA16816(acc[mi][0], aH[mi], bF[0][0], bF[0][1]);
                MMA16816(acc[mi][1], aH[mi], bF[0][2], bF[0][3]);
                MMA16816(acc[mi][2], aH[mi], bF[1][0], bF[1][1]);
                MMA16816(acc[mi][3], aH[mi], bF[1][2], bF[1][3]);
            }
            LDSM4(aL[0], WLb + aoff);
            LDSM4(aL[1], WLb + aoff + 2048);
#pragma unroll
            for (int mi = 0; mi < 2; ++mi) {      // Wlo * Xhi
                MMA16816(acc[mi][0], aL[mi], bF[0][0], bF[0][1]);
                MMA16816(acc[mi][1], aL[mi], bF[0][2], bF[0][3]);
                MMA16816(acc[mi][2], aL[mi], bF[1][0], bF[1][1]);
                MMA16816(acc[mi][3], aL[mi], bF[1][2], bF[1][3]);
            }
            LDSM4T(bF[0], XLb + bo0);
            LDSM4T(bF[1], XLb + bo1);
#pragma unroll
            for (int mi = 0; mi < 2; ++mi) {      // Whi * Xlo
                MMA16816(acc[mi][0], aH[mi], bF[0][0], bF[0][1]);
                MMA16816(acc[mi][1], aH[mi], bF[0][2], bF[0][3]);
                MMA16816(acc[mi][2], aH[mi], bF[1][0], bF[1][1]);
                MMA16816(acc[mi][3], aH[mi], bF[1][2], bF[1][3]);
            }
        }
        __syncthreads();
    }

    // ---- epilogue: write fp32 partials + Z ----
#pragma unroll
    for (int mi = 0; mi < 2; ++mi) {
        int row0 = i0 + wr * 32 + mi * 16 + (l >> 2);
#pragma unroll
        for (int ni = 0; ni < 4; ++ni) {
            int col = wc * 32 + ni * 8 + (l & 3) * 2;
            float* d0 = g_pacc + ((size_t)h * N + row0) * D + col;
            float* d1 = g_pacc + ((size_t)h * N + row0 + 8) * D + col;
            *(float2*)d0 = make_float2(acc[mi][ni][0], acc[mi][ni][1]);
            *(float2*)d1 = make_float2(acc[mi][ni][2], acc[mi][ni][3]);
        }
    }
    if (t < BM) g_pZ[h * N + i0 + t] = sZ[t];
}

// ---------------- kernel 5: combine halves + normalize ----------------
__global__ void combine_kernel(float* __restrict__ out) {
    int f   = blockIdx.x * 256 + threadIdx.x;  // float4 index
    int row = f >> 5;
    float4 s = ((const float4*)g_pacc)[f];
    float4 v = ((const float4*)g_pacc)[N * D / 4 + f];
    float inv = 1.0f / (g_pZ[row] + g_pZ[N + row]);
    s.x = (s.x + v.x) * inv;
    s.y = (s.y + v.y) * inv;
    s.z = (s.z + v.z) * inv;
    s.w = (s.w + v.w) * inv;
    ((float4*)out)[f] = s;
}

// ---------------- launch ----------------
extern "C" void kernel_launch(void* const* d_in, const int* in_sizes, int n_in,
                              void* d_out, int out_size) {
    const float* nodes = (const float*)d_in[0];  // [8192,128]
    const float* dist  = (const float*)d_in[1];  // [8192,8192]
    const float* a     = (const float*)d_in[2];  // [256,1]
    float* out = (float*)d_out;                  // [8192,128]

    cudaFuncSetAttribute(attn_kernel, cudaFuncAttributeMaxDynamicSharedMemorySize, SMEM_TOTAL);

    scores_kernel<<<N / 8, 256>>>(nodes, a);
    s2max_kernel<<<1, 256>>>();
    bprep_kernel<<<(NJT * 64 * 64) / 256, 256>>>(nodes);
    attn_kernel<<<dim3(N / BM, SPLIT), NTHREADS, SMEM_TOTAL>>>(dist);
    combine_kernel<<<N * D / 4 / 256, 256>>>(out);
}